// round 13
// baseline (speedup 1.0000x reference)
#include <cuda_runtime.h>
#include <cuda_fp16.h>
#include <cstdint>

#define D        64
#define NMAX     200000
#define NNZMAX   6400000
#define DOUT     256
#define NBLK_MAX 1024

// es staged as fp16 * 2^-10 to avoid overflow; Wb pre-scaled by 2^10 (exact)
#define ES_INV   0.0009765625f
#define WB_SCALE 1024.0f

// Scratch (device globals: allocation-free)
__device__ float  g_ego [(size_t)NMAX * D];
__device__ __half g_egoh[(size_t)NMAX * D];
__device__ float  g_side[(size_t)NMAX * D];
__device__ float  g_all [(size_t)NMAX * DOUT];
__device__ int    g_cnt [NMAX];
__device__ int    g_scan[NMAX];
__device__ int    g_rowptr[NMAX + 1];
__device__ int    g_bsum[NBLK_MAX];
__device__ int    g_bsumscan[NBLK_MAX];
__device__ int2   g_edge[NNZMAX];          // (col, val bits) packed

// ---------------------------------------------------------------------------
// MMA helpers
// ---------------------------------------------------------------------------
__device__ __forceinline__ uint32_t h2u(__half2 h) {
    return *reinterpret_cast<uint32_t*>(&h);
}
__device__ __forceinline__ void ldsm_x4(uint32_t& r0, uint32_t& r1,
                                        uint32_t& r2, uint32_t& r3, uint32_t addr) {
    asm volatile("ldmatrix.sync.aligned.m8n8.x4.shared.b16 {%0,%1,%2,%3}, [%4];"
                 : "=r"(r0), "=r"(r1), "=r"(r2), "=r"(r3) : "r"(addr));
}
__device__ __forceinline__ void ldsm_x2t(uint32_t& r0, uint32_t& r1, uint32_t addr) {
    asm volatile("ldmatrix.sync.aligned.m8n8.x2.trans.shared.b16 {%0,%1}, [%2];"
                 : "=r"(r0), "=r"(r1) : "r"(addr));
}
__device__ __forceinline__ void mma16816(float* c, const uint32_t* a,
                                         uint32_t b0, uint32_t b1) {
    asm volatile("mma.sync.aligned.m16n8k16.row.col.f32.f16.f16.f32 "
                 "{%0,%1,%2,%3}, {%4,%5,%6,%7}, {%8,%9}, {%0,%1,%2,%3};"
                 : "+f"(c[0]), "+f"(c[1]), "+f"(c[2]), "+f"(c[3])
                 : "r"(a[0]), "r"(a[1]), "r"(a[2]), "r"(a[3]), "r"(b0), "r"(b1));
}

// ---------------------------------------------------------------------------
// CSR build
// ---------------------------------------------------------------------------
__global__ void zero_cnt_kernel(int N) {
    int i = blockIdx.x * blockDim.x + threadIdx.x;
    if (i < N) g_cnt[i] = 0;
}

__global__ void hist_kernel(const int* __restrict__ rows, int nnz) {
    int e = blockIdx.x * blockDim.x + threadIdx.x;
    if (e < nnz) atomicAdd(&g_cnt[rows[e]], 1);
}

__global__ void scan_block_kernel(int N) {
    __shared__ int sh[256];
    int i = blockIdx.x * 256 + threadIdx.x;
    int v = (i < N) ? g_cnt[i] : 0;
    sh[threadIdx.x] = v;
    __syncthreads();
    for (int off = 1; off < 256; off <<= 1) {
        int t = (threadIdx.x >= off) ? sh[threadIdx.x - off] : 0;
        __syncthreads();
        sh[threadIdx.x] += t;
        __syncthreads();
    }
    if (i < N) g_scan[i] = sh[threadIdx.x] - v;
    if (threadIdx.x == 255) g_bsum[blockIdx.x] = sh[255];
}

__global__ void scan_top_kernel(int nb) {
    __shared__ int sh[NBLK_MAX];
    int i = threadIdx.x;
    int v = (i < nb) ? g_bsum[i] : 0;
    sh[i] = v;
    __syncthreads();
    for (int off = 1; off < NBLK_MAX; off <<= 1) {
        int t = (i >= off) ? sh[i - off] : 0;
        __syncthreads();
        sh[i] += t;
        __syncthreads();
    }
    if (i < nb) g_bsumscan[i] = sh[i] - v;
}

__global__ void rowptr_kernel(int N, int nnz) {
    int i = blockIdx.x * blockDim.x + threadIdx.x;
    if (i < N) {
        g_rowptr[i] = g_scan[i] + g_bsumscan[i >> 8];
        g_cnt[i] = 0;
    } else if (i == N) {
        g_rowptr[N] = nnz;
    }
}

__global__ void fill_kernel(const int* __restrict__ rows,
                            const int* __restrict__ cols,
                            const float* __restrict__ vals, int nnz) {
    int e = blockIdx.x * blockDim.x + threadIdx.x;
    if (e >= nnz) return;
    int r = rows[e];
    int p = atomicAdd(&g_cnt[r], 1);
    int d = g_rowptr[r] + p;
    g_edge[d] = make_int2(cols[e], __float_as_int(vals[e]));
}

// ---------------------------------------------------------------------------
// Init
// ---------------------------------------------------------------------------
__global__ void init_kernel(const float* __restrict__ ue,
                            const float* __restrict__ ie,
                            int n_users, int N) {
    int tid = blockIdx.x * blockDim.x + threadIdx.x;
    if (tid >= N * 16) return;
    int n = tid >> 4;
    int c = tid & 15;
    float4 v = (n < n_users)
        ? reinterpret_cast<const float4*>(ue)[(size_t)n * 16 + c]
        : reinterpret_cast<const float4*>(ie)[(size_t)(n - n_users) * 16 + c];
    reinterpret_cast<float4*>(g_ego)[(size_t)n * 16 + c] = v;
    reinterpret_cast<float4*>(g_all)[(size_t)n * 64 + c] = v;
    __half2* hr = reinterpret_cast<__half2*>(g_egoh) + (size_t)n * 32 + c * 2;
    hr[0] = __floats2half2_rn(v.x, v.y);
    hr[1] = __floats2half2_rn(v.z, v.w);
}

// ---------------------------------------------------------------------------
// Warp-per-row SpMM, paired-edge gathers:
// lanes 0-15 gather edge A's row, lanes 16-31 edge B's row (one coalesced
// 256-B LDG.64 serves 2 edges). Cross-half combine with one shfl_xor at end.
// ---------------------------------------------------------------------------
__global__ void spmm_csr_kernel(int N) {
    const int warp = (blockIdx.x * blockDim.x + threadIdx.x) >> 5;
    if (warp >= N) return;
    const int lane = threadIdx.x & 31;
    const int half = lane >> 4;        // 0: edge A, 1: edge B
    const int sub  = lane & 15;        // 8-byte chunk within row (16 x 8B = 128B)

    int e   = g_rowptr[warp];
    int end = g_rowptr[warp + 1];
    const uint2* egoh2 = reinterpret_cast<const uint2*>(g_egoh);  // 8B = 4 halfs

    float a0 = 0.f, a1 = 0.f, a2 = 0.f, a3 = 0.f;

    #define PAIR(EA, EB)                                                       \
    {                                                                          \
        int2 ea = g_edge[EA];                                                  \
        int2 eb = g_edge[EB];                                                  \
        int   col = half ? eb.x : ea.x;                                        \
        float val = __int_as_float(half ? eb.y : ea.y);                        \
        uint2 x = egoh2[(size_t)col * 16 + sub];                               \
        float2 f0 = __half22float2(*reinterpret_cast<__half2*>(&x.x));         \
        float2 f1 = __half22float2(*reinterpret_cast<__half2*>(&x.y));         \
        a0 += val * f0.x; a1 += val * f0.y;                                    \
        a2 += val * f1.x; a3 += val * f1.y;                                    \
    }

    for (; e + 3 < end; e += 4) {
        PAIR(e, e + 1);
        PAIR(e + 2, e + 3);
    }
    if (e + 1 < end) {
        PAIR(e, e + 1);
        e += 2;
    }
    if (e < end) {   // single leftover edge: both halves gather it, half 1 adds 0
        int2 ea = g_edge[e];
        int   col = ea.x;
        float val = half ? 0.f : __int_as_float(ea.y);
        uint2 x = egoh2[(size_t)col * 16 + sub];
        float2 f0 = __half22float2(*reinterpret_cast<__half2*>(&x.x));
        float2 f1 = __half22float2(*reinterpret_cast<__half2*>(&x.y));
        a0 += val * f0.x; a1 += val * f0.y;
        a2 += val * f1.x; a3 += val * f1.y;
    }
    #undef PAIR

    // combine the two half-warps (each holds partial sums of its edge subset)
    a0 += __shfl_xor_sync(0xffffffffu, a0, 16);
    a1 += __shfl_xor_sync(0xffffffffu, a1, 16);
    a2 += __shfl_xor_sync(0xffffffffu, a2, 16);
    a3 += __shfl_xor_sync(0xffffffffu, a3, 16);

    if (half == 0) {
        reinterpret_cast<float4*>(g_side)[(size_t)warp * 16 + sub] =
            make_float4(a0, a1, a2, a3);
    }
}

// ---------------------------------------------------------------------------
// Tensor-core transform. 128 threads = 4 warps; each warp does 16 nodes/tile.
// C[16x64] = s@Wg + (es*2^-10)@(Wb*2^10)   (fp16 in, fp32 acc)
// ---------------------------------------------------------------------------
__global__ void __launch_bounds__(128)
transform_mma_kernel(const float* __restrict__ Wg, const float* __restrict__ bg,
                     const float* __restrict__ Wb, const float* __restrict__ bb,
                     int N, int layer_out) {
    __shared__ alignas(16) __half sWg[64][72];
    __shared__ alignas(16) __half sWb[64][72];
    __shared__ float sBias[64];
    __shared__ alignas(16) __half sS [4][16][72];
    __shared__ alignas(16) __half sES[4][16][72];

    const int tid  = threadIdx.x;
    const int lane = tid & 31;
    const int wid  = tid >> 5;

    for (int i = tid; i < 64 * 64; i += 128) {
        int c = i >> 6, j = i & 63;
        sWg[c][j] = __float2half(Wg[i]);
        sWb[c][j] = __float2half(Wb[i] * WB_SCALE);
    }
    if (tid < 64) sBias[tid] = bg[tid] + bb[tid];
    __syncthreads();

    const int g  = lane >> 2;
    const int t4 = lane & 3;
    const int a_row  = lane & 15;
    const int a_cadd = (lane & 16) ? 8 : 0;

    const uint32_t aS_base  = (uint32_t)__cvta_generic_to_shared(&sS [wid][a_row][a_cadd]);
    const uint32_t aES_base = (uint32_t)__cvta_generic_to_shared(&sES[wid][a_row][a_cadd]);
    const int b_row = lane & 15;
    const uint32_t bWg_base = (uint32_t)__cvta_generic_to_shared(&sWg[b_row][0]);
    const uint32_t bWb_base = (uint32_t)__cvta_generic_to_shared(&sWb[b_row][0]);

    const int ntiles = (N + 63) >> 6;
    for (int tile = blockIdx.x; tile < ntiles; tile += gridDim.x) {
        const int m0 = (tile << 6) + (wid << 4);

        #pragma unroll
        for (int it = 0; it < 4; it++) {
            int idx  = it * 32 + lane;
            int nd   = idx >> 3;
            int seg  = idx & 7;
            int node = m0 + nd; if (node >= N) node = N - 1;
            const float4* sp = reinterpret_cast<const float4*>(g_side + (size_t)node * 64 + seg * 8);
            const float4* ep = reinterpret_cast<const float4*>(g_ego  + (size_t)node * 64 + seg * 8);
            float4 s0 = sp[0], s1 = sp[1];
            float4 e0 = ep[0], e1 = ep[1];
            *reinterpret_cast<uint4*>(&sS[wid][nd][seg * 8]) =
                make_uint4(h2u(__floats2half2_rn(s0.x, s0.y)),
                           h2u(__floats2half2_rn(s0.z, s0.w)),
                           h2u(__floats2half2_rn(s1.x, s1.y)),
                           h2u(__floats2half2_rn(s1.z, s1.w)));
            *reinterpret_cast<uint4*>(&sES[wid][nd][seg * 8]) =
                make_uint4(h2u(__floats2half2_rn(e0.x * s0.x * ES_INV, e0.y * s0.y * ES_INV)),
                           h2u(__floats2half2_rn(e0.z * s0.z * ES_INV, e0.w * s0.w * ES_INV)),
                           h2u(__floats2half2_rn(e1.x * s1.x * ES_INV, e1.y * s1.y * ES_INV)),
                           h2u(__floats2half2_rn(e1.z * s1.z * ES_INV, e1.w * s1.w * ES_INV)));
        }
        __syncwarp();

        uint32_t As[4][4], Aes[4][4];
        #pragma unroll
        for (int kk = 0; kk < 4; kk++) {
            ldsm_x4(As [kk][0], As [kk][1], As [kk][2], As [kk][3], aS_base  + kk * 32);
            ldsm_x4(Aes[kk][0], Aes[kk][1], Aes[kk][2], Aes[kk][3], aES_base + kk * 32);
        }
        __syncwarp();

        float acc[8][4];
        #pragma unroll
        for (int nn = 0; nn < 8; nn++) {
            acc[nn][0] = acc[nn][1] = acc[nn][2] = acc[nn][3] = 0.f;
            #pragma unroll
            for (int kk = 0; kk < 4; kk++) {
                uint32_t b0, b1;
                ldsm_x2t(b0, b1, bWg_base + kk * 16 * 144 + nn * 16);
                mma16816(acc[nn], As[kk], b0, b1);
                ldsm_x2t(b0, b1, bWb_base + kk * 16 * 144 + nn * 16);
                mma16816(acc[nn], Aes[kk], b0, b1);
            }
        }

        float sq0 = 0.f, sq1 = 0.f;
        #pragma unroll
        for (int nn = 0; nn < 8; nn++) {
            float bv0 = sBias[nn * 8 + 2 * t4];
            float bv1 = sBias[nn * 8 + 2 * t4 + 1];
            float x0 = acc[nn][0] + bv0, x1 = acc[nn][1] + bv1;
            float x2 = acc[nn][2] + bv0, x3 = acc[nn][3] + bv1;
            x0 = (x0 > 0.f) ? x0 : 0.2f * x0;
            x1 = (x1 > 0.f) ? x1 : 0.2f * x1;
            x2 = (x2 > 0.f) ? x2 : 0.2f * x2;
            x3 = (x3 > 0.f) ? x3 : 0.2f * x3;
            acc[nn][0] = x0; acc[nn][1] = x1; acc[nn][2] = x2; acc[nn][3] = x3;
            sq0 += x0 * x0 + x1 * x1;
            sq1 += x2 * x2 + x3 * x3;
        }
        sq0 += __shfl_xor_sync(0xffffffffu, sq0, 1);
        sq0 += __shfl_xor_sync(0xffffffffu, sq0, 2);
        sq1 += __shfl_xor_sync(0xffffffffu, sq1, 1);
        sq1 += __shfl_xor_sync(0xffffffffu, sq1, 2);
        float inv0 = 1.0f / fmaxf(sqrtf(sq0), 1e-12f);
        float inv1 = 1.0f / fmaxf(sqrtf(sq1), 1e-12f);

        int node0 = m0 + g;
        int node1 = m0 + g + 8;
        if (node0 < N) {
            #pragma unroll
            for (int nn = 0; nn < 8; nn++) {
                int col = nn * 8 + 2 * t4;
                float x0 = acc[nn][0], x1 = acc[nn][1];
                *reinterpret_cast<float2*>(g_ego + (size_t)node0 * 64 + col) = make_float2(x0, x1);
                *reinterpret_cast<__half2*>(g_egoh + (size_t)node0 * 64 + col) = __floats2half2_rn(x0, x1);
                *reinterpret_cast<float2*>(g_all + (size_t)node0 * DOUT + layer_out * 64 + col) =
                    make_float2(x0 * inv0, x1 * inv0);
            }
        }
        if (node1 < N) {
            #pragma unroll
            for (int nn = 0; nn < 8; nn++) {
                int col = nn * 8 + 2 * t4;
                float x2 = acc[nn][2], x3 = acc[nn][3];
                *reinterpret_cast<float2*>(g_ego + (size_t)node1 * 64 + col) = make_float2(x2, x3);
                *reinterpret_cast<__half2*>(g_egoh + (size_t)node1 * 64 + col) = __floats2half2_rn(x2, x3);
                *reinterpret_cast<float2*>(g_all + (size_t)node1 * DOUT + layer_out * 64 + col) =
                    make_float2(x2 * inv1, x3 * inv1);
            }
        }
        __syncwarp();
    }
}

// ---------------------------------------------------------------------------
// Final gather
// ---------------------------------------------------------------------------
__global__ void gather_kernel(const int* __restrict__ u,
                              const int* __restrict__ ii,
                              const int* __restrict__ jj,
                              float* __restrict__ out,
                              int B, int n_users) {
    int tid = blockIdx.x * blockDim.x + threadIdx.x;
    if (tid >= 3 * B * 64) return;
    int c     = tid & 63;
    int b     = (tid >> 6) % B;
    int which = tid / (B * 64);
    int node  = (which == 0) ? u[b]
              : (which == 1) ? n_users + ii[b]
                             : n_users + jj[b];
    reinterpret_cast<float4*>(out)[tid] =
        reinterpret_cast<const float4*>(g_all)[(size_t)node * 64 + c];
}

// ---------------------------------------------------------------------------
extern "C" void kernel_launch(void* const* d_in, const int* in_sizes, int n_in,
                              void* d_out, int out_size) {
    const int*   rows = (const int*)  d_in[0];
    const int*   cols = (const int*)  d_in[1];
    const float* vals = (const float*)d_in[2];
    const float* ue   = (const float*)d_in[3];
    const float* ie   = (const float*)d_in[4];
    const float* Wgc  = (const float*)d_in[5];
    const float* bgc  = (const float*)d_in[6];
    const float* Wbi  = (const float*)d_in[7];
    const float* bbi  = (const float*)d_in[8];
    const int*   u    = (const int*)  d_in[9];
    const int*   ii   = (const int*)  d_in[10];
    const int*   jj   = (const int*)  d_in[11];

    const int nnz     = in_sizes[0];
    const int n_users = in_sizes[3] / D;
    const int n_items = in_sizes[4] / D;
    const int N       = n_users + n_items;
    const int B       = in_sizes[9];
    const int layers  = in_sizes[5] / (D * D);

    const int TPB = 256;
    const int nb  = (N + 255) / 256;

    zero_cnt_kernel<<<(N + TPB - 1) / TPB, TPB>>>(N);
    hist_kernel<<<(nnz + TPB - 1) / TPB, TPB>>>(rows, nnz);
    scan_block_kernel<<<nb, 256>>>(N);
    scan_top_kernel<<<1, NBLK_MAX>>>(nb);
    rowptr_kernel<<<(N + 1 + TPB - 1) / TPB, TPB>>>(N, nnz);
    fill_kernel<<<(nnz + TPB - 1) / TPB, TPB>>>(rows, cols, vals, nnz);

    init_kernel<<<(N * 16 + TPB - 1) / TPB, TPB>>>(ue, ie, n_users, N);

    int tblocks = (N + 63) / 64;
    if (tblocks > 1184) tblocks = 1184;

    for (int k = 0; k < layers; k++) {
        spmm_csr_kernel<<<(N * 32 + TPB - 1) / TPB, TPB>>>(N);
        transform_mma_kernel<<<tblocks, 128>>>(Wgc + (size_t)k * D * D,
                                               bgc + (size_t)k * D,
                                               Wbi + (size_t)k * D * D,
                                               bbi + (size_t)k * D,
                                               N, k + 1);
    }

    gather_kernel<<<(3 * B * 64 + TPB - 1) / TPB, TPB>>>(u, ii, jj,
                                                         (float*)d_out, B, n_users);
}

// round 14
// speedup vs baseline: 1.2296x; 1.2296x over previous
#include <cuda_runtime.h>
#include <cuda_fp16.h>
#include <cstdint>

#define D        64
#define NMAX     200000
#define NNZMAX   6400000
#define DOUT     256
#define NBLK_MAX 1024

// es staged as fp16 * 2^-10 to avoid overflow; Wb pre-scaled by 2^10 (exact)
#define ES_INV   0.0009765625f
#define WB_SCALE 1024.0f

// Scratch (device globals: allocation-free)
__device__ float  g_ego [(size_t)NMAX * D];
__device__ __half g_egoh[(size_t)NMAX * D];
__device__ float  g_side[(size_t)NMAX * D];
__device__ float  g_all [(size_t)NMAX * DOUT];
__device__ int    g_cnt [NMAX];
__device__ int    g_scan[NMAX];
__device__ int    g_rowptr[NMAX + 1];
__device__ int    g_bsum[NBLK_MAX];
__device__ int    g_bsumscan[NBLK_MAX];
__device__ int2   g_edge[NNZMAX];          // (col, val bits) packed

// ---------------------------------------------------------------------------
// MMA helpers
// ---------------------------------------------------------------------------
__device__ __forceinline__ uint32_t h2u(__half2 h) {
    return *reinterpret_cast<uint32_t*>(&h);
}
__device__ __forceinline__ void ldsm_x4(uint32_t& r0, uint32_t& r1,
                                        uint32_t& r2, uint32_t& r3, uint32_t addr) {
    asm volatile("ldmatrix.sync.aligned.m8n8.x4.shared.b16 {%0,%1,%2,%3}, [%4];"
                 : "=r"(r0), "=r"(r1), "=r"(r2), "=r"(r3) : "r"(addr));
}
__device__ __forceinline__ void ldsm_x2t(uint32_t& r0, uint32_t& r1, uint32_t addr) {
    asm volatile("ldmatrix.sync.aligned.m8n8.x2.trans.shared.b16 {%0,%1}, [%2];"
                 : "=r"(r0), "=r"(r1) : "r"(addr));
}
__device__ __forceinline__ void mma16816(float* c, const uint32_t* a,
                                         uint32_t b0, uint32_t b1) {
    asm volatile("mma.sync.aligned.m16n8k16.row.col.f32.f16.f16.f32 "
                 "{%0,%1,%2,%3}, {%4,%5,%6,%7}, {%8,%9}, {%0,%1,%2,%3};"
                 : "+f"(c[0]), "+f"(c[1]), "+f"(c[2]), "+f"(c[3])
                 : "r"(a[0]), "r"(a[1]), "r"(a[2]), "r"(a[3]), "r"(b0), "r"(b1));
}

// ---------------------------------------------------------------------------
// CSR build
// ---------------------------------------------------------------------------
__global__ void zero_cnt_kernel(int N) {
    int i = blockIdx.x * blockDim.x + threadIdx.x;
    if (i < N) g_cnt[i] = 0;
}

__global__ void hist_kernel(const int* __restrict__ rows, int nnz) {
    int e = blockIdx.x * blockDim.x + threadIdx.x;
    if (e < nnz) atomicAdd(&g_cnt[rows[e]], 1);
}

__global__ void scan_block_kernel(int N) {
    __shared__ int sh[256];
    int i = blockIdx.x * 256 + threadIdx.x;
    int v = (i < N) ? g_cnt[i] : 0;
    sh[threadIdx.x] = v;
    __syncthreads();
    for (int off = 1; off < 256; off <<= 1) {
        int t = (threadIdx.x >= off) ? sh[threadIdx.x - off] : 0;
        __syncthreads();
        sh[threadIdx.x] += t;
        __syncthreads();
    }
    if (i < N) g_scan[i] = sh[threadIdx.x] - v;
    if (threadIdx.x == 255) g_bsum[blockIdx.x] = sh[255];
}

__global__ void scan_top_kernel(int nb) {
    __shared__ int sh[NBLK_MAX];
    int i = threadIdx.x;
    int v = (i < nb) ? g_bsum[i] : 0;
    sh[i] = v;
    __syncthreads();
    for (int off = 1; off < NBLK_MAX; off <<= 1) {
        int t = (i >= off) ? sh[i - off] : 0;
        __syncthreads();
        sh[i] += t;
        __syncthreads();
    }
    if (i < nb) g_bsumscan[i] = sh[i] - v;
}

__global__ void rowptr_kernel(int N, int nnz) {
    int i = blockIdx.x * blockDim.x + threadIdx.x;
    if (i < N) {
        g_rowptr[i] = g_scan[i] + g_bsumscan[i >> 8];
        g_cnt[i] = 0;
    } else if (i == N) {
        g_rowptr[N] = nnz;
    }
}

__global__ void fill_kernel(const int* __restrict__ rows,
                            const int* __restrict__ cols,
                            const float* __restrict__ vals, int nnz) {
    int e = blockIdx.x * blockDim.x + threadIdx.x;
    if (e >= nnz) return;
    int r = rows[e];
    int p = atomicAdd(&g_cnt[r], 1);
    int d = g_rowptr[r] + p;
    g_edge[d] = make_int2(cols[e], __float_as_int(vals[e]));
}

// ---------------------------------------------------------------------------
// Init
// ---------------------------------------------------------------------------
__global__ void init_kernel(const float* __restrict__ ue,
                            const float* __restrict__ ie,
                            int n_users, int N) {
    int tid = blockIdx.x * blockDim.x + threadIdx.x;
    if (tid >= N * 16) return;
    int n = tid >> 4;
    int c = tid & 15;
    float4 v = (n < n_users)
        ? reinterpret_cast<const float4*>(ue)[(size_t)n * 16 + c]
        : reinterpret_cast<const float4*>(ie)[(size_t)(n - n_users) * 16 + c];
    reinterpret_cast<float4*>(g_ego)[(size_t)n * 16 + c] = v;
    reinterpret_cast<float4*>(g_all)[(size_t)n * 64 + c] = v;
    __half2* hr = reinterpret_cast<__half2*>(g_egoh) + (size_t)n * 32 + c * 2;
    hr[0] = __floats2half2_rn(v.x, v.y);
    hr[1] = __floats2half2_rn(v.z, v.w);
}

// ---------------------------------------------------------------------------
// Pull-mode SpMM (R11 shape: 8 threads/row, 4-edge unroll for MLP),
// with packed int2 edge descriptors (1 LDG.64 per edge instead of 2 LDG.32).
// ---------------------------------------------------------------------------
__device__ __forceinline__ void fma8h(float* acc, uint4 x, float v) {
    float2 f;
    f = __half22float2(*reinterpret_cast<__half2*>(&x.x)); acc[0] += v * f.x; acc[1] += v * f.y;
    f = __half22float2(*reinterpret_cast<__half2*>(&x.y)); acc[2] += v * f.x; acc[3] += v * f.y;
    f = __half22float2(*reinterpret_cast<__half2*>(&x.z)); acc[4] += v * f.x; acc[5] += v * f.y;
    f = __half22float2(*reinterpret_cast<__half2*>(&x.w)); acc[6] += v * f.x; acc[7] += v * f.y;
}

__global__ void spmm_csr_kernel(int N) {
    int gid = blockIdx.x * blockDim.x + threadIdx.x;
    int row = gid >> 3;
    int c   = gid & 7;
    if (row >= N) return;
    int e   = g_rowptr[row];
    int end = g_rowptr[row + 1];
    const uint4* egoh = reinterpret_cast<const uint4*>(g_egoh);
    float acc[8] = {0.f, 0.f, 0.f, 0.f, 0.f, 0.f, 0.f, 0.f};
    for (; e + 3 < end; e += 4) {
        int2 d0 = g_edge[e];
        int2 d1 = g_edge[e + 1];
        int2 d2 = g_edge[e + 2];
        int2 d3 = g_edge[e + 3];
        uint4 x0 = egoh[(size_t)d0.x * 8 + c];
        uint4 x1 = egoh[(size_t)d1.x * 8 + c];
        uint4 x2 = egoh[(size_t)d2.x * 8 + c];
        uint4 x3 = egoh[(size_t)d3.x * 8 + c];
        fma8h(acc, x0, __int_as_float(d0.y));
        fma8h(acc, x1, __int_as_float(d1.y));
        fma8h(acc, x2, __int_as_float(d2.y));
        fma8h(acc, x3, __int_as_float(d3.y));
    }
    for (; e < end; e++) {
        int2 d0 = g_edge[e];
        uint4 x0 = egoh[(size_t)d0.x * 8 + c];
        fma8h(acc, x0, __int_as_float(d0.y));
    }
    float4* out = reinterpret_cast<float4*>(g_side) + (size_t)row * 16 + c * 2;
    out[0] = make_float4(acc[0], acc[1], acc[2], acc[3]);
    out[1] = make_float4(acc[4], acc[5], acc[6], acc[7]);
}

// ---------------------------------------------------------------------------
// Tensor-core transform. 128 threads = 4 warps; each warp does 16 nodes/tile.
// C[16x64] = s@Wg + (es*2^-10)@(Wb*2^10)   (fp16 in, fp32 acc)
// ---------------------------------------------------------------------------
__global__ void __launch_bounds__(128)
transform_mma_kernel(const float* __restrict__ Wg, const float* __restrict__ bg,
                     const float* __restrict__ Wb, const float* __restrict__ bb,
                     int N, int layer_out) {
    __shared__ alignas(16) __half sWg[64][72];
    __shared__ alignas(16) __half sWb[64][72];
    __shared__ float sBias[64];
    __shared__ alignas(16) __half sS [4][16][72];
    __shared__ alignas(16) __half sES[4][16][72];

    const int tid  = threadIdx.x;
    const int lane = tid & 31;
    const int wid  = tid >> 5;

    for (int i = tid; i < 64 * 64; i += 128) {
        int c = i >> 6, j = i & 63;
        sWg[c][j] = __float2half(Wg[i]);
        sWb[c][j] = __float2half(Wb[i] * WB_SCALE);
    }
    if (tid < 64) sBias[tid] = bg[tid] + bb[tid];
    __syncthreads();

    const int g  = lane >> 2;
    const int t4 = lane & 3;
    const int a_row  = lane & 15;
    const int a_cadd = (lane & 16) ? 8 : 0;

    const uint32_t aS_base  = (uint32_t)__cvta_generic_to_shared(&sS [wid][a_row][a_cadd]);
    const uint32_t aES_base = (uint32_t)__cvta_generic_to_shared(&sES[wid][a_row][a_cadd]);
    const int b_row = lane & 15;
    const uint32_t bWg_base = (uint32_t)__cvta_generic_to_shared(&sWg[b_row][0]);
    const uint32_t bWb_base = (uint32_t)__cvta_generic_to_shared(&sWb[b_row][0]);

    const int ntiles = (N + 63) >> 6;
    for (int tile = blockIdx.x; tile < ntiles; tile += gridDim.x) {
        const int m0 = (tile << 6) + (wid << 4);

        #pragma unroll
        for (int it = 0; it < 4; it++) {
            int idx  = it * 32 + lane;
            int nd   = idx >> 3;
            int seg  = idx & 7;
            int node = m0 + nd; if (node >= N) node = N - 1;
            const float4* sp = reinterpret_cast<const float4*>(g_side + (size_t)node * 64 + seg * 8);
            const float4* ep = reinterpret_cast<const float4*>(g_ego  + (size_t)node * 64 + seg * 8);
            float4 s0 = sp[0], s1 = sp[1];
            float4 e0 = ep[0], e1 = ep[1];
            *reinterpret_cast<uint4*>(&sS[wid][nd][seg * 8]) =
                make_uint4(h2u(__floats2half2_rn(s0.x, s0.y)),
                           h2u(__floats2half2_rn(s0.z, s0.w)),
                           h2u(__floats2half2_rn(s1.x, s1.y)),
                           h2u(__floats2half2_rn(s1.z, s1.w)));
            *reinterpret_cast<uint4*>(&sES[wid][nd][seg * 8]) =
                make_uint4(h2u(__floats2half2_rn(e0.x * s0.x * ES_INV, e0.y * s0.y * ES_INV)),
                           h2u(__floats2half2_rn(e0.z * s0.z * ES_INV, e0.w * s0.w * ES_INV)),
                           h2u(__floats2half2_rn(e1.x * s1.x * ES_INV, e1.y * s1.y * ES_INV)),
                           h2u(__floats2half2_rn(e1.z * s1.z * ES_INV, e1.w * s1.w * ES_INV)));
        }
        __syncwarp();

        uint32_t As[4][4], Aes[4][4];
        #pragma unroll
        for (int kk = 0; kk < 4; kk++) {
            ldsm_x4(As [kk][0], As [kk][1], As [kk][2], As [kk][3], aS_base  + kk * 32);
            ldsm_x4(Aes[kk][0], Aes[kk][1], Aes[kk][2], Aes[kk][3], aES_base + kk * 32);
        }
        __syncwarp();

        float acc[8][4];
        #pragma unroll
        for (int nn = 0; nn < 8; nn++) {
            acc[nn][0] = acc[nn][1] = acc[nn][2] = acc[nn][3] = 0.f;
            #pragma unroll
            for (int kk = 0; kk < 4; kk++) {
                uint32_t b0, b1;
                ldsm_x2t(b0, b1, bWg_base + kk * 16 * 144 + nn * 16);
                mma16816(acc[nn], As[kk], b0, b1);
                ldsm_x2t(b0, b1, bWb_base + kk * 16 * 144 + nn * 16);
                mma16816(acc[nn], Aes[kk], b0, b1);
            }
        }

        float sq0 = 0.f, sq1 = 0.f;
        #pragma unroll
        for (int nn = 0; nn < 8; nn++) {
            float bv0 = sBias[nn * 8 + 2 * t4];
            float bv1 = sBias[nn * 8 + 2 * t4 + 1];
            float x0 = acc[nn][0] + bv0, x1 = acc[nn][1] + bv1;
            float x2 = acc[nn][2] + bv0, x3 = acc[nn][3] + bv1;
            x0 = (x0 > 0.f) ? x0 : 0.2f * x0;
            x1 = (x1 > 0.f) ? x1 : 0.2f * x1;
            x2 = (x2 > 0.f) ? x2 : 0.2f * x2;
            x3 = (x3 > 0.f) ? x3 : 0.2f * x3;
            acc[nn][0] = x0; acc[nn][1] = x1; acc[nn][2] = x2; acc[nn][3] = x3;
            sq0 += x0 * x0 + x1 * x1;
            sq1 += x2 * x2 + x3 * x3;
        }
        sq0 += __shfl_xor_sync(0xffffffffu, sq0, 1);
        sq0 += __shfl_xor_sync(0xffffffffu, sq0, 2);
        sq1 += __shfl_xor_sync(0xffffffffu, sq1, 1);
        sq1 += __shfl_xor_sync(0xffffffffu, sq1, 2);
        float inv0 = 1.0f / fmaxf(sqrtf(sq0), 1e-12f);
        float inv1 = 1.0f / fmaxf(sqrtf(sq1), 1e-12f);

        int node0 = m0 + g;
        int node1 = m0 + g + 8;
        if (node0 < N) {
            #pragma unroll
            for (int nn = 0; nn < 8; nn++) {
                int col = nn * 8 + 2 * t4;
                float x0 = acc[nn][0], x1 = acc[nn][1];
                *reinterpret_cast<float2*>(g_ego + (size_t)node0 * 64 + col) = make_float2(x0, x1);
                *reinterpret_cast<__half2*>(g_egoh + (size_t)node0 * 64 + col) = __floats2half2_rn(x0, x1);
                *reinterpret_cast<float2*>(g_all + (size_t)node0 * DOUT + layer_out * 64 + col) =
                    make_float2(x0 * inv0, x1 * inv0);
            }
        }
        if (node1 < N) {
            #pragma unroll
            for (int nn = 0; nn < 8; nn++) {
                int col = nn * 8 + 2 * t4;
                float x2 = acc[nn][2], x3 = acc[nn][3];
                *reinterpret_cast<float2*>(g_ego + (size_t)node1 * 64 + col) = make_float2(x2, x3);
                *reinterpret_cast<__half2*>(g_egoh + (size_t)node1 * 64 + col) = __floats2half2_rn(x2, x3);
                *reinterpret_cast<float2*>(g_all + (size_t)node1 * DOUT + layer_out * 64 + col) =
                    make_float2(x2 * inv1, x3 * inv1);
            }
        }
        __syncwarp();
    }
}

// ---------------------------------------------------------------------------
// Final gather
// ---------------------------------------------------------------------------
__global__ void gather_kernel(const int* __restrict__ u,
                              const int* __restrict__ ii,
                              const int* __restrict__ jj,
                              float* __restrict__ out,
                              int B, int n_users) {
    int tid = blockIdx.x * blockDim.x + threadIdx.x;
    if (tid >= 3 * B * 64) return;
    int c     = tid & 63;
    int b     = (tid >> 6) % B;
    int which = tid / (B * 64);
    int node  = (which == 0) ? u[b]
              : (which == 1) ? n_users + ii[b]
                             : n_users + jj[b];
    reinterpret_cast<float4*>(out)[tid] =
        reinterpret_cast<const float4*>(g_all)[(size_t)node * 64 + c];
}

// ---------------------------------------------------------------------------
extern "C" void kernel_launch(void* const* d_in, const int* in_sizes, int n_in,
                              void* d_out, int out_size) {
    const int*   rows = (const int*)  d_in[0];
    const int*   cols = (const int*)  d_in[1];
    const float* vals = (const float*)d_in[2];
    const float* ue   = (const float*)d_in[3];
    const float* ie   = (const float*)d_in[4];
    const float* Wgc  = (const float*)d_in[5];
    const float* bgc  = (const float*)d_in[6];
    const float* Wbi  = (const float*)d_in[7];
    const float* bbi  = (const float*)d_in[8];
    const int*   u    = (const int*)  d_in[9];
    const int*   ii   = (const int*)  d_in[10];
    const int*   jj   = (const int*)  d_in[11];

    const int nnz     = in_sizes[0];
    const int n_users = in_sizes[3] / D;
    const int n_items = in_sizes[4] / D;
    const int N       = n_users + n_items;
    const int B       = in_sizes[9];
    const int layers  = in_sizes[5] / (D * D);

    const int TPB = 256;
    const int nb  = (N + 255) / 256;

    zero_cnt_kernel<<<(N + TPB - 1) / TPB, TPB>>>(N);
    hist_kernel<<<(nnz + TPB - 1) / TPB, TPB>>>(rows, nnz);
    scan_block_kernel<<<nb, 256>>>(N);
    scan_top_kernel<<<1, NBLK_MAX>>>(nb);
    rowptr_kernel<<<(N + 1 + TPB - 1) / TPB, TPB>>>(N, nnz);
    fill_kernel<<<(nnz + TPB - 1) / TPB, TPB>>>(rows, cols, vals, nnz);

    init_kernel<<<(N * 16 + TPB - 1) / TPB, TPB>>>(ue, ie, n_users, N);

    int tblocks = (N + 63) / 64;
    if (tblocks > 1184) tblocks = 1184;

    for (int k = 0; k < layers; k++) {
        spmm_csr_kernel<<<(N * 8 + TPB - 1) / TPB, TPB>>>(N);
        transform_mma_kernel<<<tblocks, 128>>>(Wgc + (size_t)k * D * D,
                                               bgc + (size_t)k * D,
                                               Wbi + (size_t)k * D * D,
                                               bbi + (size_t)k * D,
                                               N, k + 1);
    }

    gather_kernel<<<(3 * B * 64 + TPB - 1) / TPB, TPB>>>(u, ii, jj,
                                                         (float*)d_out, B, n_users);
}